// round 15
// baseline (speedup 1.0000x reference)
#include <cuda_runtime.h>
#include <cuda_fp16.h>

typedef unsigned long long ull;

#define NNODES 50000
#define NEDGES 1600000
#define NGRAPH 4
#define HID    64
#define NLAYERS 5
#define NTILES (NEDGES / 128)   // 12500
#define NTILE_N ((NNODES + 127) / 128)  // 391

// ---------------- device scratch ----------------
__device__ float g_h[NNODES * HID];
__device__ __align__(16) __half g_hs[NNODES * 64];    // per node: 64 fp16 (128 B)
__device__ float g_agg[NNODES * HID];
__device__ float g_pooled[NGRAPH * HID];
__device__ int   g_cnt[NGRAPH];
// per-layer fp16 weights [n][k] stride-144: B1 (2 chunks x 9216) + B2 (9216) = 27648 B
__device__ __align__(16) unsigned char g_wB[NLAYERS * 27648];  // edge
__device__ __align__(16) unsigned char g_wN[NLAYERS * 27648];  // node

// ---------------- SMEM layout: edge kernel (bytes) ----------------
#define OFF_A0   0u        // chunk0: A 128x128B SW128 (16384)
#define OFF_A1   16384u    // chunk1
#define OFF_B1   32768u    // 2 x 9216
#define OFF_B2   51200u    // 9216
#define OFF_T    60416u    // W1 tail rows 128..132 fp32 [5][64] (1280)
#define OFF_BB1  61696u
#define OFF_BB2  61952u
#define OFF_G    62208u
#define OFF_BE   62464u
#define OFF_SDST 62720u    // 2 x 128 ints (1024)
#define OFF_SEA  63744u    // 2 x 640 fp32 (5120)
#define EDGE_SMEM 68864

// ---------------- SMEM layout: node kernel (bytes) ----------------
#define NOFF_A   0u        // A 128x128B SW128 (16384)
#define NOFF_B1  16384u    // 2 x 9216
#define NOFF_B2  34816u    // 9216
#define NOFF_BB1 44032u
#define NOFF_BB2 44288u
#define NOFF_G   44544u
#define NOFF_BE  44800u
#define NODE3_SMEM 45056

// ---------------- generic helpers ----------------
__device__ __forceinline__ float silu_f(float x) {
    float t;
    asm("tanh.approx.f32 %0, %1;" : "=f"(t) : "f"(x * 0.5f));
    return x * 0.5f * t + x * 0.5f;
}
__device__ __forceinline__ ull pack2(float lo, float hi) {
    ull r;
    asm("mov.b64 %0, {%1, %2};" : "=l"(r) : "f"(lo), "f"(hi));
    return r;
}
__device__ __forceinline__ void unpack2(ull v, float& lo, float& hi) {
    asm("mov.b64 {%0, %1}, %2;" : "=f"(lo), "=f"(hi) : "l"(v));
}
__device__ __forceinline__ void red_add4(float* p, float a, float b, float c, float d) {
    asm volatile("red.global.add.v4.f32 [%0], {%1, %2, %3, %4};"
                 :: "l"(p), "f"(a), "f"(b), "f"(c), "f"(d) : "memory");
}
__device__ __forceinline__ unsigned smem_u32(const void* p) {
    unsigned a;
    asm("{ .reg .u64 t; cvta.to.shared.u64 t, %1; cvt.u32.u64 %0, t; }" : "=r"(a) : "l"(p));
    return a;
}

// ---------------- cp.async helpers ----------------
__device__ __forceinline__ void cpasync16(unsigned dst, const void* src) {
    asm volatile("cp.async.cg.shared.global [%0], [%1], 16;" :: "r"(dst), "l"(src) : "memory");
}
#define CP_COMMIT() asm volatile("cp.async.commit_group;" ::: "memory")
#define CP_WAIT1()  asm volatile("cp.async.wait_group 1;" ::: "memory")
#define CP_WAIT0()  asm volatile("cp.async.wait_group 0;" ::: "memory")

// ---------------- mma.sync helpers (fp16 in, fp32 accum) ----------------
__device__ __forceinline__ void ldsm4(unsigned* r, unsigned addr) {
    asm volatile("ldmatrix.sync.aligned.m8n8.x4.shared.b16 {%0,%1,%2,%3}, [%4];"
                 : "=r"(r[0]), "=r"(r[1]), "=r"(r[2]), "=r"(r[3]) : "r"(addr));
}
__device__ __forceinline__ void mma16816(float* c, const unsigned* a, unsigned b0, unsigned b1) {
    asm volatile("mma.sync.aligned.m16n8k16.row.col.f32.f16.f16.f32 "
                 "{%0,%1,%2,%3}, {%4,%5,%6,%7}, {%8,%9}, {%0,%1,%2,%3};"
                 : "+f"(c[0]), "+f"(c[1]), "+f"(c[2]), "+f"(c[3])
                 : "r"(a[0]), "r"(a[1]), "r"(a[2]), "r"(a[3]), "r"(b0), "r"(b1));
}

// ---------------- zero kernels ----------------
__global__ void zero_agg_kernel() {
    int i = blockIdx.x * blockDim.x + threadIdx.x;
    for (; i < NNODES * HID; i += gridDim.x * blockDim.x) g_agg[i] = 0.f;
}
__global__ void zero_pool_kernel() {
    int t = threadIdx.x;
    if (t < NGRAPH * HID) g_pooled[t] = 0.f;
    if (t < NGRAPH) g_cnt[t] = 0;
}

// ---------------- weight prep: fp32 -> fp16, padded [n][k] ----------------
__global__ void prep_weights(const float* __restrict__ eW1, const float* __restrict__ eW2,
                             const float* __restrict__ nW1, const float* __restrict__ nW2) {
    int idx = blockIdx.x * blockDim.x + threadIdx.x;
    if (idx >= NLAYERS * 24576) return;
    int l = idx / 24576, r = idx % 24576;
    int isNode = (r >= 12288);
    if (isNode) r -= 12288;
    unsigned char* base = (isNode ? g_wN : g_wB) + l * 27648;
    float w;
    unsigned off;
    if (r < 8192) {
        int c = r >> 12, rr = r & 4095, n = rr >> 6, kk = rr & 63;
        if (isNode) w = nW1[l * 128 * 64 + (c * 64 + kk) * 64 + n];
        else        w = eW1[l * 133 * 64 + (c * 64 + kk) * 64 + n];
        off = (unsigned)(c * 9216 + n * 144 + kk * 2);
    } else {
        int rr = r - 8192, n = rr >> 6, kk = rr & 63;
        if (isNode) w = nW2[l * 4096 + kk * 64 + n];
        else        w = eW2[l * 4096 + kk * 64 + n];
        off = (unsigned)(18432 + n * 144 + kk * 2);
    }
    *(__half*)(base + off) = __float2half_rn(w);
}

// ---------------- encoder (also writes fp16 g_hs) ----------------
__global__ void __launch_bounds__(128) encoder_kernel(
    const float* __restrict__ x, const int* __restrict__ batch,
    const float* __restrict__ caseP, const float* __restrict__ bcP,
    const float* __restrict__ W1, const float* __restrict__ b1,
    const float* __restrict__ W2, const float* __restrict__ b2,
    const float* __restrict__ gam, const float* __restrict__ bet)
{
    __shared__ float sW1[16 * 64];
    __shared__ float sW2[64 * 64];
    __shared__ float sb1[64], sb2[64], sg[64], sbe[64];
    __shared__ float sy[4][64];
    int tid = threadIdx.x;
    for (int i = tid; i < 16 * 64; i += 128) sW1[i] = W1[i];
    for (int i = tid; i < 64 * 64; i += 128) sW2[i] = W2[i];
    if (tid < 64) { sb1[tid] = b1[tid]; sb2[tid] = b2[tid]; sg[tid] = gam[tid]; sbe[tid] = bet[tid]; }
    __syncthreads();

    int lane = tid & 31, warp = tid >> 5;
    int j0 = lane, j1 = lane + 32;
    for (int n = blockIdx.x * 4 + warp; n < NNODES; n += gridDim.x * 4) {
        float in[16];
        const float* xr = x + n * 8;
#pragma unroll
        for (int k = 0; k < 8; ++k) in[k] = xr[k];
        int b = batch[n];
#pragma unroll
        for (int k = 0; k < 4; ++k) in[8 + k]  = caseP[b * 4 + k];
#pragma unroll
        for (int k = 0; k < 4; ++k) in[12 + k] = bcP[b * 4 + k];

        float a0 = sb1[j0], a1 = sb1[j1];
#pragma unroll
        for (int k = 0; k < 16; ++k) {
            a0 = fmaf(in[k], sW1[k * 64 + j0], a0);
            a1 = fmaf(in[k], sW1[k * 64 + j1], a1);
        }
        a0 = silu_f(a0); a1 = silu_f(a1);
        sy[warp][j0] = a0; sy[warp][j1] = a1;
        __syncwarp();
        float z0 = sb2[j0], z1 = sb2[j1];
#pragma unroll 4
        for (int k = 0; k < 64; ++k) {
            float v = sy[warp][k];
            z0 = fmaf(v, sW2[k * 64 + j0], z0);
            z1 = fmaf(v, sW2[k * 64 + j1], z1);
        }
        float s = z0 + z1, ss = z0 * z0 + z1 * z1;
#pragma unroll
        for (int o = 16; o > 0; o >>= 1) {
            s  += __shfl_xor_sync(0xffffffffu, s, o);
            ss += __shfl_xor_sync(0xffffffffu, ss, o);
        }
        float m = s * (1.f / 64.f);
        float rs = rsqrtf(ss * (1.f / 64.f) - m * m + 1e-5f);
        float v0 = (z0 - m) * rs * sg[j0] + sbe[j0];
        float v1 = (z1 - m) * rs * sg[j1] + sbe[j1];
        g_h[n * HID + j0] = v0;
        g_h[n * HID + j1] = v1;
        g_hs[n * 64 + j0] = __float2half_rn(v0);
        g_hs[n * 64 + j1] = __float2half_rn(v1);
        __syncwarp();
    }
}

// ---------------- edge MLP v12 (unchanged from R13) ----------------
__global__ void __launch_bounds__(128, 3) edge12_kernel(
    const int* __restrict__ ei, const float* __restrict__ ea, int layer,
    const float* __restrict__ W1full, const float* __restrict__ b1,
    const float* __restrict__ b2,
    const float* __restrict__ gam, const float* __restrict__ bet)
{
    extern __shared__ unsigned char sm[];
    const unsigned sbase = smem_u32(sm);
    const int tid = threadIdx.x;
    const int lane = tid & 31, warp = tid >> 5;
    const int gID = lane >> 2, tig = lane & 3;
    const int lt = lane >> 3, lr = lane & 7;

    {
        const uint4* srcw = (const uint4*)(g_wB + layer * 27648);
        uint4* dstw = (uint4*)(sm + OFF_B1);
#pragma unroll 4
        for (int i = tid; i < 1728; i += 128) dstw[i] = srcw[i];
    }
    for (int i = tid; i < 320; i += 128) ((float*)(sm + OFF_T))[i] = W1full[128 * 64 + i];
    if (tid < 64) {
        ((float*)(sm + OFF_BB1))[tid] = b1[tid];
        ((float*)(sm + OFF_BB2))[tid] = b2[tid];
        ((float*)(sm + OFF_G))[tid]   = gam[tid];
        ((float*)(sm + OFF_BE))[tid]  = bet[tid];
    }

    const unsigned aOff = (unsigned)((warp * 32 + (lt & 1) * 8 + lr) * 128
                                     + ((unsigned)((lt >> 1) << 4) ^ ((unsigned)lr << 4)));
    const unsigned bLane = (unsigned)(((lt >> 1) * 8 + lr) * 144 + ((lt & 1) << 4));
    const float* bb1 = (const float*)(sm + OFF_BB1);
    int* sdst_all = (int*)(sm + OFF_SDST);
    float* sea_all = (float*)(sm + OFF_SEA);

    const int grow = warp * 32 + (lane >> 3);
    const int cp = lane & 7;
    const unsigned gcol = (unsigned)(cp * 16);

    const int t0 = blockIdx.x;
    {
        const int e0 = t0 * 128;
        sdst_all[tid] = ei[NEDGES + e0 + tid];
        for (int i = tid; i < 640; i += 128) sea_all[i] = ea[(ull)e0 * 5 + i];
#pragma unroll
        for (int i = 0; i < 8; ++i) {
            int row = grow + 4 * i;
            int node = ei[NEDGES + e0 + row];
            cpasync16(sbase + OFF_A0 + (unsigned)(row * 128)
                          + (gcol ^ (((unsigned)row & 7u) << 4)),
                      (const unsigned char*)g_hs + (ull)node * 128 + cp * 16);
        }
        CP_COMMIT();
#pragma unroll
        for (int i = 0; i < 8; ++i) {
            int row = grow + 4 * i;
            int node = ei[e0 + row];
            cpasync16(sbase + OFF_A1 + (unsigned)(row * 128)
                          + (gcol ^ (((unsigned)row & 7u) << 4)),
                      (const unsigned char*)g_hs + (ull)node * 128 + cp * 16);
        }
        CP_COMMIT();
    }

    int it = 0;
    for (int t = t0; t < NTILES; t += gridDim.x, ++it) {
        const int p = it & 1;
        const int* sdst = sdst_all + p * 128;
        const float* sea = sea_all + p * 640;

        int tn = t + gridDim.x;
        if (tn >= NTILES) tn = t;
        const int e0n = tn * 128;

        float acc[2][8][4];
#pragma unroll
        for (int nt = 0; nt < 8; ++nt) {
            float2 bv = *(const float2*)(bb1 + nt * 8 + 2 * tig);
#pragma unroll
            for (int mt = 0; mt < 2; ++mt) {
                acc[mt][nt][0] = bv.x; acc[mt][nt][1] = bv.y;
                acc[mt][nt][2] = bv.x; acc[mt][nt][3] = bv.y;
            }
        }

        CP_WAIT1();
        __syncthreads();
        {
            const unsigned bB = sbase + OFF_B1 + bLane;
#pragma unroll
            for (int kt = 0; kt < 4; ++kt) {
                const unsigned kx = (unsigned)(kt * 32);
                unsigned a0[4], a1[4];
                ldsm4(a0, sbase + OFF_A0 + (aOff ^ kx));
                ldsm4(a1, sbase + OFF_A0 + ((aOff + 2048u) ^ kx));
                unsigned bf[4][4];
#pragma unroll
                for (int q = 0; q < 4; ++q) ldsm4(bf[q], bB + q * 2304u + kx);
#pragma unroll
                for (int q = 0; q < 4; ++q) {
                    mma16816(acc[0][2 * q],     a0, bf[q][0], bf[q][1]);
                    mma16816(acc[0][2 * q + 1], a0, bf[q][2], bf[q][3]);
                    mma16816(acc[1][2 * q],     a1, bf[q][0], bf[q][1]);
                    mma16816(acc[1][2 * q + 1], a1, bf[q][2], bf[q][3]);
                }
            }
        }
        __syncthreads();

        sdst_all[(p ^ 1) * 128 + tid] = ei[NEDGES + e0n + tid];
        for (int i = tid; i < 640; i += 128) sea_all[(p ^ 1) * 640 + i] = ea[(ull)e0n * 5 + i];
#pragma unroll
        for (int i = 0; i < 8; ++i) {
            int row = grow + 4 * i;
            int node = ei[NEDGES + e0n + row];
            cpasync16(sbase + OFF_A0 + (unsigned)(row * 128)
                          + (gcol ^ (((unsigned)row & 7u) << 4)),
                      (const unsigned char*)g_hs + (ull)node * 128 + cp * 16);
        }
        CP_COMMIT();

        CP_WAIT1();
        __syncthreads();
        {
            const unsigned bB = sbase + OFF_B1 + 9216u + bLane;
#pragma unroll
            for (int kt = 0; kt < 4; ++kt) {
                const unsigned kx = (unsigned)(kt * 32);
                unsigned a0[4], a1[4];
                ldsm4(a0, sbase + OFF_A1 + (aOff ^ kx));
                ldsm4(a1, sbase + OFF_A1 + ((aOff + 2048u) ^ kx));
                unsigned bf[4][4];
#pragma unroll
                for (int q = 0; q < 4; ++q) ldsm4(bf[q], bB + q * 2304u + kx);
#pragma unroll
                for (int q = 0; q < 4; ++q) {
                    mma16816(acc[0][2 * q],     a0, bf[q][0], bf[q][1]);
                    mma16816(acc[0][2 * q + 1], a0, bf[q][2], bf[q][3]);
                    mma16816(acc[1][2 * q],     a1, bf[q][0], bf[q][1]);
                    mma16816(acc[1][2 * q + 1], a1, bf[q][2], bf[q][3]);
                }
            }
        }

        float eav[2][2][5];
#pragma unroll
        for (int mt = 0; mt < 2; ++mt)
#pragma unroll
            for (int h = 0; h < 2; ++h) {
                const float* er = sea + (warp * 32 + mt * 16 + h * 8 + gID) * 5;
#pragma unroll
                for (int j = 0; j < 5; ++j) eav[mt][h][j] = er[j];
            }
        unsigned uh[2][2][8];
#pragma unroll
        for (int nt = 0; nt < 8; ++nt) {
            float2 w[5];
#pragma unroll
            for (int j = 0; j < 5; ++j)
                w[j] = *(const float2*)(sm + OFF_T + (unsigned)((j * 64 + nt * 8 + tig * 2) * 4));
#pragma unroll
            for (int mt = 0; mt < 2; ++mt)
#pragma unroll
                for (int h = 0; h < 2; ++h) {
                    float y0 = acc[mt][nt][2 * h], y1 = acc[mt][nt][2 * h + 1];
#pragma unroll
                    for (int j = 0; j < 5; ++j) {
                        y0 = fmaf(eav[mt][h][j], w[j].x, y0);
                        y1 = fmaf(eav[mt][h][j], w[j].y, y1);
                    }
                    __half2 hb = __float22half2_rn(make_float2(silu_f(y0), silu_f(y1)));
                    uh[mt][h][nt] = *(unsigned*)&hb;
                }
        }

        float acc2[2][8][4];
#pragma unroll
        for (int nt = 0; nt < 8; ++nt) {
            float2 bv = *(const float2*)(sm + OFF_BB2 + (unsigned)((nt * 8 + tig * 2) * 4));
#pragma unroll
            for (int mt = 0; mt < 2; ++mt) {
                acc2[mt][nt][0] = bv.x; acc2[mt][nt][1] = bv.y;
                acc2[mt][nt][2] = bv.x; acc2[mt][nt][3] = bv.y;
            }
        }
        const unsigned b2B = sbase + OFF_B2 + bLane;
#pragma unroll
        for (int kt = 0; kt < 4; ++kt) {
            unsigned bf[4][4];
#pragma unroll
            for (int q = 0; q < 4; ++q) ldsm4(bf[q], b2B + q * 2304u + kt * 32u);
            unsigned ah0[4] = {uh[0][0][2 * kt], uh[0][1][2 * kt], uh[0][0][2 * kt + 1], uh[0][1][2 * kt + 1]};
            unsigned ah1[4] = {uh[1][0][2 * kt], uh[1][1][2 * kt], uh[1][0][2 * kt + 1], uh[1][1][2 * kt + 1]};
#pragma unroll
            for (int q = 0; q < 4; ++q) {
                mma16816(acc2[0][2 * q],     ah0, bf[q][0], bf[q][1]);
                mma16816(acc2[0][2 * q + 1], ah0, bf[q][2], bf[q][3]);
                mma16816(acc2[1][2 * q],     ah1, bf[q][0], bf[q][1]);
                mma16816(acc2[1][2 * q + 1], ah1, bf[q][2], bf[q][3]);
            }
        }
        __syncthreads();

#pragma unroll
        for (int i = 0; i < 8; ++i) {
            int row = grow + 4 * i;
            int node = ei[e0n + row];
            cpasync16(sbase + OFF_A1 + (unsigned)(row * 128)
                          + (gcol ^ (((unsigned)row & 7u) << 4)),
                      (const unsigned char*)g_hs + (ull)node * 128 + cp * 16);
        }
        CP_COMMIT();

        float mArr[2][2], rsArr[2][2];
#pragma unroll
        for (int mt = 0; mt < 2; ++mt)
#pragma unroll
            for (int h = 0; h < 2; ++h) {
                float s = 0.f, ssum = 0.f;
#pragma unroll
                for (int nt = 0; nt < 8; ++nt) {
                    float v0 = acc2[mt][nt][2 * h], v1 = acc2[mt][nt][2 * h + 1];
                    s += v0 + v1; ssum += v0 * v0 + v1 * v1;
                }
                s    += __shfl_xor_sync(0xffffffffu, s, 1);
                ssum += __shfl_xor_sync(0xffffffffu, ssum, 1);
                s    += __shfl_xor_sync(0xffffffffu, s, 2);
                ssum += __shfl_xor_sync(0xffffffffu, ssum, 2);
                float m = s * (1.f / 64.f);
                mArr[mt][h]  = m;
                rsArr[mt][h] = rsqrtf(ssum * (1.f / 64.f) - m * m + 1e-5f);
            }
        const int cq = (tig & 1) * 2 + (tig >> 1);
        float4 gq[4], beq[4];
#pragma unroll
        for (int j = 0; j < 4; ++j) {
            gq[j]  = ((const float4*)(sm + OFF_G))[4 * j + cq];
            beq[j] = ((const float4*)(sm + OFF_BE))[4 * j + cq];
        }
        const unsigned colb = (unsigned)((tig & 1) * 8 + (tig >> 1) * 4);
#pragma unroll
        for (int mt = 0; mt < 2; ++mt)
#pragma unroll
            for (int h = 0; h < 2; ++h) {
                int row = warp * 32 + mt * 16 + h * 8 + gID;
                float* ag = g_agg + (ull)sdst[row] * 64 + colb;
                float m = mArr[mt][h], rs = rsArr[mt][h];
#pragma unroll
                for (int j = 0; j < 4; ++j) {
                    ull p0 = pack2(acc2[mt][2 * j][2 * h],     acc2[mt][2 * j][2 * h + 1]);
                    ull p1 = pack2(acc2[mt][2 * j + 1][2 * h], acc2[mt][2 * j + 1][2 * h + 1]);
                    ull sel = (tig & 1) ? p0 : p1;
                    ull rv = __shfl_xor_sync(0xffffffffu, sel, 1);
                    float q0, q1, q2, q3;
                    if (tig & 1) { unpack2(rv, q0, q1); unpack2(p1, q2, q3); }
                    else         { unpack2(p0, q0, q1); unpack2(rv, q2, q3); }
                    float o0 = (q0 - m) * rs * gq[j].x + beq[j].x;
                    float o1 = (q1 - m) * rs * gq[j].y + beq[j].y;
                    float o2 = (q2 - m) * rs * gq[j].z + beq[j].z;
                    float o3 = (q3 - m) * rs * gq[j].w + beq[j].w;
                    red_add4(ag + 16 * j, o0, o1, o2, o3);
                }
            }
    }
    CP_WAIT0();
}

// ---------------- node MLP v4: persistent, fp16 mma, fused agg-zeroing ----------------
__global__ void __launch_bounds__(128, 3) node4_kernel(
    int layer,
    const float* __restrict__ b1, const float* __restrict__ b2,
    const float* __restrict__ gam, const float* __restrict__ bet)
{
    extern __shared__ unsigned char sm[];
    const unsigned sbase = smem_u32(sm);
    const int tid = threadIdx.x;
    const int lane = tid & 31, warp = tid >> 5;
    const int gID = lane >> 2, tig = lane & 3;
    const int lt = lane >> 3, lr = lane & 7;

    {
        const uint4* srcw = (const uint4*)(g_wN + layer * 27648);
        uint4* dstw = (uint4*)(sm + NOFF_B1);
#pragma unroll 4
        for (int i = tid; i < 1728; i += 128) dstw[i] = srcw[i];
    }
    if (tid < 64) {
        ((float*)(sm + NOFF_BB1))[tid] = b1[tid];
        ((float*)(sm + NOFF_BB2))[tid] = b2[tid];
        ((float*)(sm + NOFF_G))[tid]   = gam[tid];
        ((float*)(sm + NOFF_BE))[tid]  = bet[tid];
    }
    __syncthreads();

    const unsigned aOff = (unsigned)((warp * 32 + (lt & 1) * 8 + lr) * 128
                                     + ((unsigned)((lt >> 1) << 4) ^ ((unsigned)lr << 4)));
    const unsigned bLane = (unsigned)(((lt >> 1) * 8 + lr) * 144 + ((lt & 1) << 4));
    const float* bb1 = (const float*)(sm + NOFF_BB1);

    for (int t = blockIdx.x; t < NTILE_N; t += gridDim.x) {
        const int n0 = t * 128;
        __syncthreads();   // previous tile's ldsm reads of A done

        // acc init with b1
        float acc[2][8][4];
#pragma unroll
        for (int nt = 0; nt < 8; ++nt) {
            float2 bv = *(const float2*)(bb1 + nt * 8 + 2 * tig);
#pragma unroll
            for (int mt = 0; mt < 2; ++mt) {
                acc[mt][nt][0] = bv.x; acc[mt][nt][1] = bv.y;
                acc[mt][nt][2] = bv.x; acc[mt][nt][3] = bv.y;
            }
        }

        // ---- stage chunk0: g_hs rows (fp16, coalesced) ----
        for (int idx = tid; idx < 1024; idx += 128) {
            int row = idx >> 3, c = idx & 7;
            int node = n0 + row;
            if (node >= NNODES) node = NNODES - 1;
            uint4 v = *(const uint4*)((const unsigned char*)g_hs + (ull)node * 128 + c * 16);
            *(uint4*)(sm + NOFF_A + (unsigned)(row * 128)
                         + (((unsigned)c * 16u) ^ (((unsigned)row & 7u) << 4))) = v;
        }
        __syncthreads();
        {
            const unsigned bB = sbase + NOFF_B1 + bLane;
#pragma unroll
            for (int kt = 0; kt < 4; ++kt) {
                const unsigned kx = (unsigned)(kt * 32);
                unsigned a0[4], a1[4];
                ldsm4(a0, sbase + NOFF_A + (aOff ^ kx));
                ldsm4(a1, sbase + NOFF_A + ((aOff + 2048u) ^ kx));
                unsigned bf[4][4];
#pragma unroll
                for (int q = 0; q < 4; ++q) ldsm4(bf[q], bB + q * 2304u + kx);
#pragma unroll
                for (int q = 0; q < 4; ++q) {
                    mma16816(acc[0][2 * q],     a0, bf[q][0], bf[q][1]);
                    mma16816(acc[0][2 * q + 1], a0, bf[q][2], bf[q][3]);
                    mma16816(acc[1][2 * q],     a1, bf[q][0], bf[q][1]);
                    mma16816(acc[1][2 * q + 1], a1, bf[q][2], bf[q][3]);
                }
            }
        }
        __syncthreads();

        // ---- stage chunk1: g_agg rows fp32 -> fp16; zero g_agg behind the read ----
        for (int idx = tid; idx < 2048; idx += 128) {
            int row = idx >> 4, c = idx & 15;
            int node = n0 + row;
            bool real = (node < NNODES);
            if (!real) node = NNODES - 1;
            float4 v = *(const float4*)(g_agg + (ull)node * 64 + c * 4);
            if (real) *(float4*)(g_agg + (ull)node * 64 + c * 4) = make_float4(0.f, 0.f, 0.f, 0.f);
            __half2 h01 = __float22half2_rn(make_float2(v.x, v.y));
            __half2 h23 = __float22half2_rn(make_float2(v.z, v.w));
            ull pv = ((ull)*(unsigned*)&h23 << 32) | *(unsigned*)&h01;
            *(ull*)(sm + NOFF_A + (unsigned)(row * 128)
                       + ((((unsigned)(c >> 1)) * 16u) ^ (((unsigned)row & 7u) << 4))
                       + (unsigned)((c & 1) * 8)) = pv;
        }
        __syncthreads();
        {
            const unsigned bB = sbase + NOFF_B1 + 9216u + bLane;
#pragma unroll
            for (int kt = 0; kt < 4; ++kt) {
                const unsigned kx = (unsigned)(kt * 32);
                unsigned a0[4], a1[4];
                ldsm4(a0, sbase + NOFF_A + (aOff ^ kx));
                ldsm4(a1, sbase + NOFF_A + ((aOff + 2048u) ^ kx));
                unsigned bf[4][4];
#pragma unroll
                for (int q = 0; q < 4; ++q) ldsm4(bf[q], bB + q * 2304u + kx);
#pragma unroll
                for (int q = 0; q < 4; ++q) {
                    mma16816(acc[0][2 * q],     a0, bf[q][0], bf[q][1]);
                    mma16816(acc[0][2 * q + 1], a0, bf[q][2], bf[q][3]);
                    mma16816(acc[1][2 * q],     a1, bf[q][0], bf[q][1]);
                    mma16816(acc[1][2 * q + 1], a1, bf[q][2], bf[q][3]);
                }
            }
        }

        // ---- epilogue1: silu -> fp16 regs ----
        unsigned uh[2][2][8];
#pragma unroll
        for (int nt = 0; nt < 8; ++nt)
#pragma unroll
            for (int mt = 0; mt < 2; ++mt)
#pragma unroll
                for (int h = 0; h < 2; ++h) {
                    __half2 hb = __float22half2_rn(make_float2(silu_f(acc[mt][nt][2 * h]),
                                                               silu_f(acc[mt][nt][2 * h + 1])));
                    uh[mt][h][nt] = *(unsigned*)&hb;
                }

        // ---- GEMM2 ----
        float acc2[2][8][4];
#pragma unroll
        for (int nt = 0; nt < 8; ++nt) {
            float2 bv = *(const float2*)(sm + NOFF_BB2 + (unsigned)((nt * 8 + tig * 2) * 4));
#pragma unroll
            for (int mt = 0; mt < 2; ++mt) {
                acc2[mt][nt][0] = bv.x; acc2[mt][nt][1] = bv.y;
                acc2[mt][nt][2] = bv.x; acc2[mt][nt][3] = bv.y;
            }
        }
        const unsigned b2B = sbase + NOFF_B2 + bLane;
#pragma unroll
        for (int kt = 0; kt < 4; ++kt) {
            unsigned bf[4][4];
#pragma unroll
            for (int q = 0; q < 4; ++q) ldsm4(bf[q], b2B + q * 2304u + kt * 32u);
            unsigned ah0[4] = {uh[0][0][2 * kt], uh[0][1][2 * kt], uh[0][0][2 * kt + 1], uh[0][1][2 * kt + 1]};
            unsigned ah1[4] = {uh[1][0][2 * kt], uh[1][1][2 * kt], uh[1][0][2 * kt + 1], uh[1][1][2 * kt + 1]};
#pragma unroll
            for (int q = 0; q < 4; ++q) {
                mma16816(acc2[0][2 * q],     ah0, bf[q][0], bf[q][1]);
                mma16816(acc2[0][2 * q + 1], ah0, bf[q][2], bf[q][3]);
                mma16816(acc2[1][2 * q],     ah1, bf[q][0], bf[q][1]);
                mma16816(acc2[1][2 * q + 1], ah1, bf[q][2], bf[q][3]);
            }
        }

        // ---- epilogue2: LN + residual (disjoint RMW per thread) ----
        float mArr[2][2], rsArr[2][2];
#pragma unroll
        for (int mt = 0; mt < 2; ++mt)
#pragma unroll
            for (int h = 0; h < 2; ++h) {
                float s = 0.f, ssum = 0.f;
#pragma unroll
                for (int nt = 0; nt < 8; ++nt) {
                    float v0 = acc2[mt][nt][2 * h], v1 = acc2[mt][nt][2 * h + 1];
                    s += v0 + v1; ssum += v0 * v0 + v1 * v1;
                }
                s    += __shfl_xor_sync(0xffffffffu, s, 1);
                ssum += __shfl_xor_sync(0xffffffffu, ssum, 1);
                s    += __shfl_xor_sync(0xffffffffu, s, 2);
                ssum += __shfl_xor_sync(0xffffffffu, ssum, 2);
                float m = s * (1.f / 64.f);
                mArr[mt][h]  = m;
                rsArr[mt][h] = rsqrtf(ssum * (1.f / 64.f) - m * m + 1e-5f);
            }
        const int cq = (tig & 1) * 2 + (tig >> 1);
        float4 gq[4], beq[4];
#pragma unroll
        for (int j = 0; j < 4; ++j) {
            gq[j]  = ((const float4*)(sm + NOFF_G))[4 * j + cq];
            beq[j] = ((const float4*)(sm + NOFF_BE))[4 * j + cq];
        }
        const unsigned colb = (unsigned)((tig & 1) * 8 + (tig >> 1) * 4);
#pragma unroll
        for (int mt = 0; mt < 2; ++mt)
#pragma unroll
            for (int h = 0; h < 2; ++h) {
                int row = warp * 32 + mt * 16 + h * 8 + gID;
                int node = n0 + row;
                bool valid = (node < NNODES);
                float m = mArr[mt][h], rs = rsArr[mt][h];
#pragma unroll
                for (int j = 0; j < 4; ++j) {
                    ull p0 = pack2(acc2[mt][2 * j][2 * h],     acc2[mt][2 * j][2 * h + 1]);
                    ull p1 = pack2(acc2[mt][2 * j + 1][2 * h], acc2[mt][2 * j + 1][2 * h + 1]);
                    ull sel = (tig & 1) ? p0 : p1;
                    ull rv = __shfl_xor_sync(0xffffffffu, sel, 1);
                    float q0, q1, q2, q3;
                    if (tig & 1) { unpack2(rv, q0, q1); unpack2(p1, q2, q3); }
                    else         { unpack2(p0, q0, q1); unpack2(rv, q2, q3); }
                    if (valid) {
                        float* hp = g_h + (ull)node * 64 + colb + 16 * j;
                        float4 hv = *(float4*)hp;
                        hv.x += (q0 - m) * rs * gq[j].x + beq[j].x;
                        hv.y += (q1 - m) * rs * gq[j].y + beq[j].y;
                        hv.z += (q2 - m) * rs * gq[j].z + beq[j].z;
                        hv.w += (q3 - m) * rs * gq[j].w + beq[j].w;
                        *(float4*)hp = hv;
                        __half2 h01 = __float22half2_rn(make_float2(hv.x, hv.y));
                        __half2 h23 = __float22half2_rn(make_float2(hv.z, hv.w));
                        ull pv = ((ull)*(unsigned*)&h23 << 32) | *(unsigned*)&h01;
                        *(ull*)(g_hs + (ull)node * 64 + colb + 16 * j) = pv;
                    }
                }
            }
    }
}

// ---------------- local decoder ----------------
__global__ void __launch_bounds__(128) dec_local_kernel(
    const float* __restrict__ W1, const float* __restrict__ b1,
    const float* __restrict__ W2, const float* __restrict__ b2,
    float* __restrict__ out)
{
    __shared__ float sW1[64 * 64];
    __shared__ float sW2[64 * 6];
    __shared__ float sb1[64];
    __shared__ float sb2[8];
    __shared__ float sy[4][64];
    int tid = threadIdx.x;
    for (int i = tid; i < 64 * 64; i += 128) sW1[i] = W1[i];
    for (int i = tid; i < 64 * 6; i += 128) sW2[i] = W2[i];
    if (tid < 64) sb1[tid] = b1[tid];
    if (tid < 6)  sb2[tid] = b2[tid];
    __syncthreads();

    int lane = tid & 31, warp = tid >> 5;
    int j0 = lane, j1 = lane + 32;
    for (int n = blockIdx.x * 4 + warp; n < NNODES; n += gridDim.x * 4) {
        const float4* Hr = reinterpret_cast<const float4*>(g_h + n * HID);
        float a0 = sb1[j0], a1 = sb1[j1];
#pragma unroll 4
        for (int c = 0; c < 16; ++c) {
            float4 v = Hr[c];
            const float* w = sW1 + 4 * c * 64;
            a0 = fmaf(v.x, w[j0], a0);           a1 = fmaf(v.x, w[j1], a1);
            a0 = fmaf(v.y, w[64 + j0], a0);      a1 = fmaf(v.y, w[64 + j1], a1);
            a0 = fmaf(v.z, w[128 + j0], a0);     a1 = fmaf(v.z, w[128 + j1], a1);
            a0 = fmaf(v.w, w[192 + j0], a0);     a1 = fmaf(v.w, w[192 + j1], a1);
        }
        a0 = silu_f(a0); a1 = silu_f(a1);
        sy[warp][j0] = a0; sy[warp][j1] = a1;
        __syncwarp();
        if (lane < 6) {
            float o = sb2[lane];
#pragma unroll 8
            for (int k = 0; k < 64; ++k) o = fmaf(sy[warp][k], sW2[k * 6 + lane], o);
            out[n * 6 + lane] = o;
        }
        __syncwarp();
    }
}

// ---------------- pooling ----------------
__global__ void __launch_bounds__(256) pool_kernel(const int* __restrict__ batch)
{
    __shared__ float sacc[NGRAPH * HID];
    __shared__ int   scnt[NGRAPH];
    int tid = threadIdx.x;
    sacc[tid] = 0.f;
    if (tid < NGRAPH) scnt[tid] = 0;
    __syncthreads();
    int j = tid & 63;
    int r = tid >> 6;
    int base = blockIdx.x * 512;
    int end = min(base + 512, NNODES);
    for (int n = base + r; n < end; n += 4) {
        int b = batch[n];
        atomicAdd(&sacc[b * HID + j], g_h[n * HID + j]);
        if (j == 0) atomicAdd(&scnt[b], 1);
    }
    __syncthreads();
    atomicAdd(&g_pooled[tid], sacc[tid]);
    if (tid < NGRAPH) atomicAdd(&g_cnt[tid], scnt[tid]);
}

// ---------------- global decoder ----------------
__global__ void dec_global_kernel(
    const float* __restrict__ W1, const float* __restrict__ b1,
    const float* __restrict__ W2, const float* __restrict__ b2,
    float* __restrict__ out)
{
    __shared__ float sy[NGRAPH][32];
    int g = threadIdx.x >> 5;
    int lane = threadIdx.x & 31;
    float inv = 1.f / fmaxf((float)g_cnt[g], 1.f);
    float a = b1[lane];
#pragma unroll 8
    for (int k = 0; k < 64; ++k)
        a = fmaf(g_pooled[g * HID + k] * inv, W1[k * 32 + lane], a);
    a = silu_f(a);
    sy[g][lane] = a;
    __syncwarp();
    if (lane < 4) {
        float o = b2[lane];
#pragma unroll 8
        for (int k = 0; k < 32; ++k) o = fmaf(sy[g][k], W2[k * 4 + lane], o);
        out[g * 4 + lane] = o;
    }
}

// ---------------- launch ----------------
extern "C" void kernel_launch(void* const* d_in, const int* in_sizes, int n_in,
                              void* d_out, int out_size)
{
    (void)in_sizes; (void)n_in; (void)out_size;
    const float* x      = (const float*)d_in[0];
    const int*   ei     = (const int*)  d_in[1];
    const float* ea     = (const float*)d_in[2];
    const int*   batch  = (const int*)  d_in[3];
    const float* caseP  = (const float*)d_in[4];
    const float* bcP    = (const float*)d_in[5];
    const float* encW1  = (const float*)d_in[6];
    const float* encb1  = (const float*)d_in[7];
    const float* encW2  = (const float*)d_in[8];
    const float* encb2  = (const float*)d_in[9];
    const float* encg   = (const float*)d_in[10];
    const float* encbe  = (const float*)d_in[11];
    const float* eW1    = (const float*)d_in[12];
    const float* eb1    = (const float*)d_in[13];
    const float* eW2    = (const float*)d_in[14];
    const float* eb2    = (const float*)d_in[15];
    const float* egm    = (const float*)d_in[16];
    const float* ebe    = (const float*)d_in[17];
    const float* nW1    = (const float*)d_in[18];
    const float* nb1    = (const float*)d_in[19];
    const float* nW2    = (const float*)d_in[20];
    const float* nb2    = (const float*)d_in[21];
    const float* ngm    = (const float*)d_in[22];
    const float* nbe    = (const float*)d_in[23];
    const float* dlW1   = (const float*)d_in[24];
    const float* dlb1   = (const float*)d_in[25];
    const float* dlW2   = (const float*)d_in[26];
    const float* dlb2   = (const float*)d_in[27];
    const float* dgW1   = (const float*)d_in[28];
    const float* dgb1   = (const float*)d_in[29];
    const float* dgW2   = (const float*)d_in[30];
    const float* dgb2   = (const float*)d_in[31];
    float* out = (float*)d_out;

    cudaFuncSetAttribute(edge12_kernel, cudaFuncAttributeMaxDynamicSharedMemorySize, EDGE_SMEM);
    cudaFuncSetAttribute(node4_kernel, cudaFuncAttributeMaxDynamicSharedMemorySize, NODE3_SMEM);

    prep_weights<<<(NLAYERS * 24576 + 255) / 256, 256>>>(eW1, eW2, nW1, nW2);
    encoder_kernel<<<200, 128>>>(x, batch, caseP, bcP,
                                 encW1, encb1, encW2, encb2, encg, encbe);
    zero_agg_kernel<<<512, 256>>>();   // layer-0 init (later layers zeroed by node4)

    for (int l = 0; l < NLAYERS; ++l) {
        edge12_kernel<<<444, 128, EDGE_SMEM>>>(
            ei, ea, l,
            eW1 + l * 133 * 64, eb1 + l * 64, eb2 + l * 64,
            egm + l * 64, ebe + l * 64);
        node4_kernel<<<148, 128, NODE3_SMEM>>>(
            l, nb1 + l * 64, nb2 + l * 64,
            ngm + l * 64, nbe + l * 64);
    }

    zero_pool_kernel<<<1, 256>>>();
    dec_local_kernel<<<200, 128>>>(dlW1, dlb1, dlW2, dlb2, out);
    pool_kernel<<<(NNODES + 511) / 512, 256>>>(batch);
    dec_global_kernel<<<1, 128>>>(dgW1, dgb1, dgW2, dgb2, out + NNODES * 6);
}